// round 15
// baseline (speedup 1.0000x reference)
#include <cuda_runtime.h>
#include <cuda_fp16.h>
#include <cstdint>

#define M_Q   4096
#define N_B   65536
#define D_DIM 128
#define KNN   9
#define MTILE 128
#define NTILE 128
#define NSPLIT 9                      // one-wave grid: 32*9 = 288 CTAs, 2/SM
#define NT_TOTAL (N_B / NTILE)        // 512 n-tiles
#define THREADS 384                   // 8 tensor warps + 4 SIMT warps
#define PART_STRIDE 12
#define NLISTS (NSPLIT * 2)           // 9 tensor + 9 simt
#define TILE_HALFS (128 * D_DIM)      // 16384 halves = 32KB per packed tile
#define NQTILES (M_Q / MTILE)         // 32
#define TCOLS 112                     // tensor columns (14 n8-blocks, 7 ldsm pos)

// ---------------------------------------------------------------------------
// Device-global scratch
// ---------------------------------------------------------------------------
__device__ __align__(16) float g_bsq[N_B];
__device__ __align__(16) float g_qsq[M_Q];
__device__ __align__(16) float g_part[NLISTS * M_Q * PART_STRIDE];
__device__ __align__(16) __half g_bt[(size_t)N_B * D_DIM];   // packed pre-swizzled
__device__ __align__(16) __half g_qt[(size_t)M_Q * D_DIM];
__device__ int g_cnt[NQTILES];        // per-qtile completion counters

// ---------------------------------------------------------------------------
// SMEM: A 32KB, B 2x32KB, bsq 2x512B, mbarriers + flag
// ---------------------------------------------------------------------------
#define OFF_A    0
#define OFF_B    32768
#define OFF_BSQ  (32768 + 2 * 32768)        // 98304
#define OFF_MBAR (OFF_BSQ + 2 * 512)        // 99328
#define SMEM_SZ  (OFF_MBAR + 64)

// ---------------------------------------------------------------------------
// PTX helpers (sm_90-baseline)
// ---------------------------------------------------------------------------
__device__ __forceinline__ uint32_t smem_u32(const void* p) {
    uint32_t a;
    asm("{ .reg .u64 t; cvta.to.shared.u64 t, %1; cvt.u32.u64 %0, t; }" : "=r"(a) : "l"(p));
    return a;
}
__device__ __forceinline__ void ldsm4(uint32_t* r, uint32_t addr) {
    asm volatile("ldmatrix.sync.aligned.m8n8.x4.shared.b16 {%0,%1,%2,%3}, [%4];"
                 : "=r"(r[0]), "=r"(r[1]), "=r"(r[2]), "=r"(r[3]) : "r"(addr));
}
__device__ __forceinline__ void lds128(uint4& v, uint32_t addr) {
    asm volatile("ld.shared.v4.u32 {%0,%1,%2,%3}, [%4];"
                 : "=r"(v.x), "=r"(v.y), "=r"(v.z), "=r"(v.w) : "r"(addr));
}
__device__ __forceinline__ void mma16816_f16(uint32_t* c, const uint32_t* a, const uint32_t* b) {
    asm volatile(
        "mma.sync.aligned.m16n8k16.row.col.f16.f16.f16.f16 "
        "{%0,%1}, {%2,%3,%4,%5}, {%6,%7}, {%0,%1};"
        : "+r"(c[0]), "+r"(c[1])
        : "r"(a[0]), "r"(a[1]), "r"(a[2]), "r"(a[3]), "r"(b[0]), "r"(b[1]));
}
#define MBAR_INIT(a, c) \
    asm volatile("mbarrier.init.shared.b64 [%0], %1;" :: "r"(a), "r"(c) : "memory")
#define MBAR_EXPECT_TX(a, tx) \
    asm volatile("mbarrier.arrive.expect_tx.shared.b64 _, [%0], %1;" :: "r"(a), "r"(tx) : "memory")
#define MBAR_WAIT(a, ph) do {                                                   \
    asm volatile(                                                               \
        "{\n\t.reg .pred P1;\n\t"                                               \
        "WAIT_LOOP_%=:\n\t"                                                     \
        "mbarrier.try_wait.parity.acquire.cta.shared::cta.b64 P1, [%0], %1, 0x989680;\n\t" \
        "@P1 bra.uni WAIT_DONE_%=;\n\t"                                         \
        "bra.uni WAIT_LOOP_%=;\n\t"                                             \
        "WAIT_DONE_%=:\n\t}"                                                    \
        :: "r"(a), "r"(ph) : "memory");                                         \
} while (0)
__device__ __forceinline__ void bulk_g2s(uint32_t dst, const void* src,
                                         uint32_t bytes, uint32_t mbar) {
    asm volatile(
        "cp.async.bulk.shared::cluster.global.mbarrier::complete_tx::bytes "
        "[%0], [%1], %2, [%3];"
        :: "r"(dst), "l"(src), "r"(bytes), "r"(mbar) : "memory");
}

// ---------------------------------------------------------------------------
// Pre-pass: fp32 -> fp16 packed pre-swizzled tiles + fused squared norms.
// Also resets the per-qtile completion counters.
// ---------------------------------------------------------------------------
__global__ void pack_norms_kernel(const float4* __restrict__ src,
                                  uint4* __restrict__ dst,
                                  float* __restrict__ nrm, int nchunks) {
    if (blockIdx.x == 0 && threadIdx.x < NQTILES) g_cnt[threadIdx.x] = 0;
    int i = blockIdx.x * blockDim.x + threadIdx.x;
    if (i >= nchunks) return;
    int vec = i >> 4, c = i & 15;
    int tile = vec >> 7, r = vec & 127;
    float4 a = src[2 * i];
    float4 b = src[2 * i + 1];
    __half2 h0 = __floats2half2_rn(a.x, a.y);
    __half2 h1 = __floats2half2_rn(a.z, a.w);
    __half2 h2 = __floats2half2_rn(b.x, b.y);
    __half2 h3 = __floats2half2_rn(b.z, b.w);
    uint4 o;
    o.x = *(uint32_t*)&h0; o.y = *(uint32_t*)&h1;
    o.z = *(uint32_t*)&h2; o.w = *(uint32_t*)&h3;
    uint32_t off = (uint32_t)tile * 32768 + r * 256 + (((uint32_t)(c ^ (r & 7))) << 4);
    dst[off >> 4] = o;

    float s = a.x * a.x + a.y * a.y + a.z * a.z + a.w * a.w
            + b.x * b.x + b.y * b.y + b.z * b.z + b.w * b.w;
#pragma unroll
    for (int offv = 8; offv; offv >>= 1) s += __shfl_xor_sync(0xffffffffu, s, offv);
    if (c == 0) nrm[vec] = s;
}

// ---------------------------------------------------------------------------
// Streaming top-9
// ---------------------------------------------------------------------------
__device__ __forceinline__ void top9f(float s, float (&h)[KNN], float& thr) {
    if (s < thr) {
        bool done = false;
#pragma unroll
        for (int i = 0; i < KNN; i++)
            if (!done && h[i] == thr) { h[i] = s; done = true; }
        float m = h[0];
#pragma unroll
        for (int i = 1; i < KNN; i++) m = fmaxf(m, h[i]);
        thr = m;
    }
}

// ---------------------------------------------------------------------------
// Main kernel: hybrid tensor(cols 0-111, 8 warps) + SIMT(cols 112-127,
// 4 warps, one thread per row) + fused finalize. grid (32,9), 2 CTAs/SM.
// ---------------------------------------------------------------------------
__global__ void __launch_bounds__(THREADS, 2) knn_main_kernel(float* __restrict__ out) {
    extern __shared__ char smem[];
    const uint32_t sm = smem_u32(smem);
    const int tid  = threadIdx.x;
    const int wid  = tid >> 5;
    const int lane = tid & 31;
    const int g    = lane >> 2;
    const int tig  = lane & 3;
    const int qtile = blockIdx.x;
    const int qbase = qtile * MTILE;
    const int b0  = (NT_TOTAL * blockIdx.y) / NSPLIT;
    const int cnt = (NT_TOTAL * (blockIdx.y + 1)) / NSPLIT - b0;
    const float INF = __int_as_float(0x7f800000);
    const unsigned FULL = 0xffffffffu;

    if (tid == 0) { MBAR_INIT(sm + OFF_MBAR, 1); MBAR_INIT(sm + OFF_MBAR + 8, 1); }
    __syncthreads();

    if (tid == 0) {
        MBAR_EXPECT_TX(sm + OFF_MBAR, 32768u + 32768u + 512u);
        bulk_g2s(sm + OFF_A, g_qt + (size_t)qtile * TILE_HALFS, 32768u, sm + OFF_MBAR);
        bulk_g2s(sm + OFF_B, g_bt + (size_t)b0 * TILE_HALFS, 32768u, sm + OFF_MBAR);
        bulk_g2s(sm + OFF_BSQ, g_bsq + b0 * NTILE, 512u, sm + OFF_MBAR);
        MBAR_EXPECT_TX(sm + OFF_MBAR + 8, 32768u + 512u);
        bulk_g2s(sm + OFF_B + 32768, g_bt + (size_t)(b0 + 1) * TILE_HALFS, 32768u,
                 sm + OFF_MBAR + 8);
        bulk_g2s(sm + OFF_BSQ + 512, g_bsq + (b0 + 1) * NTILE, 512u, sm + OFF_MBAR + 8);
    }

    MBAR_WAIT(sm + OFF_MBAR, 0);   // A + B0 + bsq0 ready (all threads)

    // tensor lane invariants + A fragment preload (tensor warps only)
    const int rA   = lane & 15;
    const int shiA = lane >> 4;
    const int rB   = (lane & 7) + ((lane >> 4) << 3);
    const int shiB = (lane >> 3) & 1;
    uint32_t aF[8][4];
    if (wid < 8) {
        const uint32_t arow = sm + OFF_A + (wid * 16 + rA) * 256;
#pragma unroll
        for (int s = 0; s < 8; s++)
            ldsm4(aF[s], arow + ((((uint32_t)(2 * s + shiA)) ^ (uint32_t)(rA & 7)) << 4));
    }

    // heaps: tensor threads use heap0/heap1 (rows g, g+8 of band);
    // SIMT threads use heap0 only (their single row), heap1 unused.
    float heap0[KNN], heap1[KNN];
    float thr0 = INF, thr1 = INF;
#pragma unroll
    for (int i = 0; i < KNN; i++) { heap0[i] = INF; heap1[i] = INF; }

    // SIMT lane invariants
    const int sid = (wid - 8) * 32 + lane;   // row 0..127 (valid when wid>=8)
    const uint32_t arow_s = sm + OFF_A + sid * 256;
    const int rs = sid & 7;

#pragma unroll 1
    for (int t = 0; t < cnt; t++) {
        const int buf = t & 1;
        if (t > 0) MBAR_WAIT(sm + OFF_MBAR + buf * 8, (t >> 1) & 1);

        const uint32_t Bb = sm + OFF_B + buf * 32768;
        const float* bsq = (const float*)(smem + OFF_BSQ + buf * 512);
        const float2* bq2 = (const float2*)bsq;

        if (wid < 8) {
            // ========= tensor path: cols 0..111 (positions 0..6) =========
            // half A: positions 0..3 (8 blocks, cols 0..63)
            {
                uint32_t acc[8][2];
#pragma unroll
                for (int f = 0; f < 8; f++) { acc[f][0] = 0u; acc[f][1] = 0u; }
#pragma unroll
                for (int s = 0; s < 8; s++) {
                    const uint32_t segoff =
                        (((uint32_t)(2 * s + shiB)) ^ (uint32_t)(rB & 7)) << 4;
#pragma unroll
                    for (int p = 0; p < 4; p++) {
                        uint32_t bf[4];
                        ldsm4(bf, Bb + (p * 16 + rB) * 256 + segoff);
                        mma16816_f16(acc[2 * p],     aF[s], bf);
                        mma16816_f16(acc[2 * p + 1], aF[s], bf + 2);
                    }
                }
#pragma unroll
                for (int f = 0; f < 8; f++) {
                    float2 bq = bq2[4 * f + tig];
                    float2 v0 = __half22float2(*(const __half2*)&acc[f][0]);
                    float2 v1 = __half22float2(*(const __half2*)&acc[f][1]);
                    top9f(fmaf(-2.0f, v0.x, bq.x), heap0, thr0);
                    top9f(fmaf(-2.0f, v0.y, bq.y), heap0, thr0);
                    top9f(fmaf(-2.0f, v1.x, bq.x), heap1, thr1);
                    top9f(fmaf(-2.0f, v1.y, bq.y), heap1, thr1);
                }
            }
            // half B: positions 4..6 (6 blocks, cols 64..111)
            {
                uint32_t acc[6][2];
#pragma unroll
                for (int f = 0; f < 6; f++) { acc[f][0] = 0u; acc[f][1] = 0u; }
#pragma unroll
                for (int s = 0; s < 8; s++) {
                    const uint32_t segoff =
                        (((uint32_t)(2 * s + shiB)) ^ (uint32_t)(rB & 7)) << 4;
#pragma unroll
                    for (int p = 0; p < 3; p++) {
                        uint32_t bf[4];
                        ldsm4(bf, Bb + ((p + 4) * 16 + rB) * 256 + segoff);
                        mma16816_f16(acc[2 * p],     aF[s], bf);
                        mma16816_f16(acc[2 * p + 1], aF[s], bf + 2);
                    }
                }
#pragma unroll
                for (int f = 0; f < 6; f++) {
                    float2 bq = bq2[32 + 4 * f + tig];
                    float2 v0 = __half22float2(*(const __half2*)&acc[f][0]);
                    float2 v1 = __half22float2(*(const __half2*)&acc[f][1]);
                    top9f(fmaf(-2.0f, v0.x, bq.x), heap0, thr0);
                    top9f(fmaf(-2.0f, v0.y, bq.y), heap0, thr0);
                    top9f(fmaf(-2.0f, v1.x, bq.x), heap1, thr1);
                    top9f(fmaf(-2.0f, v1.y, bq.y), heap1, thr1);
                }
            }
        } else {
            // ========= SIMT path: row sid, cols 112..127 =========
            float acc[16];
#pragma unroll
            for (int n = 0; n < 16; n++) acc[n] = 0.0f;

#pragma unroll
            for (int kp = 0; kp < 2; kp++) {
#pragma unroll
                for (int pr = 0; pr < 4; pr++) {
                    const int c0 = kp * 8 + pr * 2;
                    uint4 av0, av1;
                    lds128(av0, arow_s + (((uint32_t)(c0 ^ rs)) << 4));
                    lds128(av1, arow_s + (((uint32_t)((c0 + 1) ^ rs)) << 4));
                    const __half2* a2 = (const __half2*)&av0;   // av0,av1 contiguous? no —
                    __half2 a[8];
                    a[0] = *(__half2*)&av0.x; a[1] = *(__half2*)&av0.y;
                    a[2] = *(__half2*)&av0.z; a[3] = *(__half2*)&av0.w;
                    a[4] = *(__half2*)&av1.x; a[5] = *(__half2*)&av1.y;
                    a[6] = *(__half2*)&av1.z; a[7] = *(__half2*)&av1.w;
                    (void)a2;
#pragma unroll
                    for (int n = 0; n < 16; n++) {
                        const int col = TCOLS + n;
                        const uint32_t brow = Bb + col * 256;
                        uint4 bv0, bv1;
                        lds128(bv0, brow + (((uint32_t)(c0 ^ (col & 7))) << 4));
                        lds128(bv1, brow + (((uint32_t)((c0 + 1) ^ (col & 7))) << 4));
                        __half2 s2 = __half2half2(__ushort_as_half(0));
                        s2 = __hfma2(a[0], *(__half2*)&bv0.x, s2);
                        s2 = __hfma2(a[1], *(__half2*)&bv0.y, s2);
                        s2 = __hfma2(a[2], *(__half2*)&bv0.z, s2);
                        s2 = __hfma2(a[3], *(__half2*)&bv0.w, s2);
                        s2 = __hfma2(a[4], *(__half2*)&bv1.x, s2);
                        s2 = __hfma2(a[5], *(__half2*)&bv1.y, s2);
                        s2 = __hfma2(a[6], *(__half2*)&bv1.z, s2);
                        s2 = __hfma2(a[7], *(__half2*)&bv1.w, s2);
                        float2 f = __half22float2(s2);
                        acc[n] += f.x + f.y;
                    }
                }
            }
#pragma unroll
            for (int n = 0; n < 16; n++) {
                float s = fmaf(-2.0f, acc[n], bsq[TCOLS + n]);
                top9f(s, heap0, thr0);
            }
        }

        __syncthreads();
        if (t + 2 < cnt && tid == 0) {
            MBAR_EXPECT_TX(sm + OFF_MBAR + buf * 8, 32768u + 512u);
            bulk_g2s(sm + OFF_B + buf * 32768,
                     g_bt + (size_t)(b0 + t + 2) * TILE_HALFS, 32768u,
                     sm + OFF_MBAR + buf * 8);
            bulk_g2s(sm + OFF_BSQ + buf * 512, g_bsq + (b0 + t + 2) * NTILE, 512u,
                     sm + OFF_MBAR + buf * 8);
        }
    }

    // ---- flush lists ----
    if (wid < 8) {
        // quad merge (safe: sources never mutate, only tig==0 inserts)
#pragma unroll
        for (int src = 1; src < 4; src++) {
#pragma unroll
            for (int i = 0; i < KNN; i++) {
                float v0 = __shfl_sync(FULL, heap0[i], (lane & ~3) + src);
                float v1 = __shfl_sync(FULL, heap1[i], (lane & ~3) + src);
                if (tig == 0) { top9f(v0, heap0, thr0); top9f(v1, heap1, thr1); }
            }
        }
        if (tig == 0) {
            const int row0 = qbase + wid * 16 + g;
            size_t p0 = ((size_t)blockIdx.y * M_Q + row0) * PART_STRIDE;
            size_t p1 = ((size_t)blockIdx.y * M_Q + row0 + 8) * PART_STRIDE;
#pragma unroll
            for (int r = 0; r < KNN; r++) {
                g_part[p0 + r] = heap0[r];
                g_part[p1 + r] = heap1[r];
            }
        }
    } else {
        // SIMT: single owner per row, no merge needed. list = 9 + blockIdx.y
        size_t p0 = ((size_t)(NSPLIT + blockIdx.y) * M_Q + qbase + sid) * PART_STRIDE;
#pragma unroll
        for (int r = 0; r < KNN; r++) g_part[p0 + r] = heap0[r];
    }

    // ---- fused finalize: last CTA of this qtile merges 18 lists -> out
    __threadfence();
    __syncthreads();
    int* flag = (int*)(smem + OFF_MBAR + 32);
    if (tid == 0) *flag = atomicAdd(&g_cnt[qtile], 1);
    __syncthreads();
    if (*flag == NSPLIT - 1) {
        if (tid < MTILE) {
            const int qi = qbase + tid;
            float heap[KNN], thr = INF;
#pragma unroll
            for (int i = 0; i < KNN; i++) heap[i] = INF;
#pragma unroll 1
            for (int l = 0; l < NLISTS; l++) {
                const float* p = &g_part[((size_t)l * M_Q + qi) * PART_STRIDE];
#pragma unroll
                for (int r = 0; r < KNN; r++) top9f(p[r], heap, thr);
            }
            float qsq = g_qsq[qi];
            float sum = 0.0f;
#pragma unroll
            for (int i = 0; i < KNN; i++) sum += sqrtf(fmaxf(heap[i] + qsq, 0.0f));
            out[qi] = sum * (1.0f / KNN);
        }
    }
}

// ---------------------------------------------------------------------------
extern "C" void kernel_launch(void* const* d_in, const int* in_sizes, int n_in,
                              void* d_out, int out_size)
{
    const float* q = (const float*)d_in[0];   // features    [4096,128]
    const float* b = (const float*)d_in[1];   // memory_bank [65536,128]
    if (n_in >= 2 && in_sizes[0] > in_sizes[1]) {   // defensive ordering
        const float* tmp = q; q = b; b = tmp;
    }
    float* out = (float*)d_out;

    static uint4* p_bt = nullptr;
    static uint4* p_qt = nullptr;
    static float *p_bsq = nullptr, *p_qsq = nullptr;
    if (!p_bt) {
        cudaGetSymbolAddress((void**)&p_bt, g_bt);
        cudaGetSymbolAddress((void**)&p_qt, g_qt);
        cudaGetSymbolAddress((void**)&p_bsq, g_bsq);
        cudaGetSymbolAddress((void**)&p_qsq, g_qsq);
    }

    cudaFuncSetAttribute(knn_main_kernel,
                         cudaFuncAttributeMaxDynamicSharedMemorySize, SMEM_SZ);

    pack_norms_kernel<<<N_B * 16 / 256, 256>>>((const float4*)b, p_bt, p_bsq, N_B * 16);
    pack_norms_kernel<<<M_Q * 16 / 256, 256>>>((const float4*)q, p_qt, p_qsq, M_Q * 16);

    dim3 grid(M_Q / MTILE, NSPLIT);
    knn_main_kernel<<<grid, THREADS, SMEM_SZ>>>(out);
}

// round 16
// speedup vs baseline: 1.5948x; 1.5948x over previous
#include <cuda_runtime.h>
#include <cuda_fp16.h>
#include <cstdint>

#define M_Q   4096
#define N_B   65536
#define D_DIM 128
#define KNN   9
#define MTILE 128
#define NTILE 128
#define NSPLIT 9                      // one-wave grid: 32*9 = 288 CTAs, 2/SM
#define NT_TOTAL (N_B / NTILE)        // 512 n-tiles
#define THREADS 256
#define PART_STRIDE 12
#define NLISTS NSPLIT
#define TILE_HALFS (128 * D_DIM)      // 16384 halves = 32KB per packed tile
#define NQTILES (M_Q / MTILE)         // 32
#define BCHUNKS (N_B * 16)            // 16B output chunks for bank
#define QCHUNKS (M_Q * 16)

// ---------------------------------------------------------------------------
// Device-global scratch
// ---------------------------------------------------------------------------
__device__ __align__(16) float g_bsq[N_B];
__device__ __align__(16) float g_qsq[M_Q];
__device__ __align__(16) float g_part[NLISTS * M_Q * PART_STRIDE];
__device__ __align__(16) __half g_bt[(size_t)N_B * D_DIM];   // packed pre-swizzled
__device__ __align__(16) __half g_qt[(size_t)M_Q * D_DIM];
__device__ int g_cnt[NQTILES];        // per-qtile completion counters

// ---------------------------------------------------------------------------
// SMEM: A 32KB, B 2x32KB, bsq 2x512B, mbarriers + flag
// ---------------------------------------------------------------------------
#define OFF_A    0
#define OFF_B    32768
#define OFF_BSQ  (32768 + 2 * 32768)        // 98304
#define OFF_MBAR (OFF_BSQ + 2 * 512)        // 99328
#define SMEM_SZ  (OFF_MBAR + 64)

// ---------------------------------------------------------------------------
// PTX helpers (sm_90-baseline)
// ---------------------------------------------------------------------------
__device__ __forceinline__ uint32_t smem_u32(const void* p) {
    uint32_t a;
    asm("{ .reg .u64 t; cvta.to.shared.u64 t, %1; cvt.u32.u64 %0, t; }" : "=r"(a) : "l"(p));
    return a;
}
__device__ __forceinline__ void ldsm4(uint32_t* r, uint32_t addr) {
    asm volatile("ldmatrix.sync.aligned.m8n8.x4.shared.b16 {%0,%1,%2,%3}, [%4];"
                 : "=r"(r[0]), "=r"(r[1]), "=r"(r[2]), "=r"(r[3]) : "r"(addr));
}
__device__ __forceinline__ void mma16816_f16(uint32_t* c, const uint32_t* a, const uint32_t* b) {
    asm volatile(
        "mma.sync.aligned.m16n8k16.row.col.f16.f16.f16.f16 "
        "{%0,%1}, {%2,%3,%4,%5}, {%6,%7}, {%0,%1};"
        : "+r"(c[0]), "+r"(c[1])
        : "r"(a[0]), "r"(a[1]), "r"(a[2]), "r"(a[3]), "r"(b[0]), "r"(b[1]));
}
#define MBAR_INIT(a, c) \
    asm volatile("mbarrier.init.shared.b64 [%0], %1;" :: "r"(a), "r"(c) : "memory")
#define MBAR_EXPECT_TX(a, tx) \
    asm volatile("mbarrier.arrive.expect_tx.shared.b64 _, [%0], %1;" :: "r"(a), "r"(tx) : "memory")
#define MBAR_WAIT(a, ph) do {                                                   \
    asm volatile(                                                               \
        "{\n\t.reg .pred P1;\n\t"                                               \
        "WAIT_LOOP_%=:\n\t"                                                     \
        "mbarrier.try_wait.parity.acquire.cta.shared::cta.b64 P1, [%0], %1, 0x989680;\n\t" \
        "@P1 bra.uni WAIT_DONE_%=;\n\t"                                         \
        "bra.uni WAIT_LOOP_%=;\n\t"                                             \
        "WAIT_DONE_%=:\n\t}"                                                    \
        :: "r"(a), "r"(ph) : "memory");                                         \
} while (0)
__device__ __forceinline__ void bulk_g2s(uint32_t dst, const void* src,
                                         uint32_t bytes, uint32_t mbar) {
    asm volatile(
        "cp.async.bulk.shared::cluster.global.mbarrier::complete_tx::bytes "
        "[%0], [%1], %2, [%3];"
        :: "r"(dst), "l"(src), "r"(bytes), "r"(mbar) : "memory");
}

// ---------------------------------------------------------------------------
// Pre-pass (single launch): fp32 -> fp16 packed pre-swizzled tiles + norms
// for BOTH tensors; also resets the per-qtile completion counters.
// Blocks [0, BCHUNKS/256) handle the bank; the rest handle the queries.
// ---------------------------------------------------------------------------
__device__ __forceinline__ void pack_one(const float4* __restrict__ src,
                                         uint4* __restrict__ dst,
                                         float* __restrict__ nrm, int i) {
    int vec = i >> 4, c = i & 15;
    int tile = vec >> 7, r = vec & 127;
    float4 a = src[2 * i];
    float4 b = src[2 * i + 1];
    __half2 h0 = __floats2half2_rn(a.x, a.y);
    __half2 h1 = __floats2half2_rn(a.z, a.w);
    __half2 h2 = __floats2half2_rn(b.x, b.y);
    __half2 h3 = __floats2half2_rn(b.z, b.w);
    uint4 o;
    o.x = *(uint32_t*)&h0; o.y = *(uint32_t*)&h1;
    o.z = *(uint32_t*)&h2; o.w = *(uint32_t*)&h3;
    uint32_t off = (uint32_t)tile * 32768 + r * 256 + (((uint32_t)(c ^ (r & 7))) << 4);
    dst[off >> 4] = o;

    float s = a.x * a.x + a.y * a.y + a.z * a.z + a.w * a.w
            + b.x * b.x + b.y * b.y + b.z * b.z + b.w * b.w;
#pragma unroll
    for (int offv = 8; offv; offv >>= 1) s += __shfl_xor_sync(0xffffffffu, s, offv);
    if (c == 0) nrm[vec] = s;
}

__global__ void pack_norms_kernel(const float4* __restrict__ bank,
                                  const float4* __restrict__ qry,
                                  uint4* __restrict__ bdst, uint4* __restrict__ qdst,
                                  float* __restrict__ bnrm, float* __restrict__ qnrm) {
    if (blockIdx.x == 0 && threadIdx.x < NQTILES) g_cnt[threadIdx.x] = 0;
    int i = blockIdx.x * blockDim.x + threadIdx.x;
    if (i < BCHUNKS) {
        pack_one(bank, bdst, bnrm, i);
    } else {
        pack_one(qry, qdst, qnrm, i - BCHUNKS);
    }
}

// ---------------------------------------------------------------------------
// Streaming top-9
// ---------------------------------------------------------------------------
__device__ __forceinline__ void top9f(float s, float (&h)[KNN], float& thr) {
    if (s < thr) {
        bool done = false;
#pragma unroll
        for (int i = 0; i < KNN; i++)
            if (!done && h[i] == thr) { h[i] = s; done = true; }
        float m = h[0];
#pragma unroll
        for (int i = 1; i < KNN; i++) m = fmaxf(m, h[i]);
        thr = m;
    }
}

// ---------------------------------------------------------------------------
// Main kernel: R14 structure (grid 32x9, 2 CTAs/SM) + fused finalize.
// ---------------------------------------------------------------------------
__global__ void __launch_bounds__(THREADS, 2) knn_main_kernel(float* __restrict__ out) {
    extern __shared__ char smem[];
    const uint32_t sm = smem_u32(smem);
    const int tid  = threadIdx.x;
    const int wid  = tid >> 5;
    const int lane = tid & 31;
    const int g    = lane >> 2;
    const int tig  = lane & 3;
    const int qtile = blockIdx.x;
    const int qbase = qtile * MTILE;
    const int b0  = (NT_TOTAL * blockIdx.y) / NSPLIT;
    const int cnt = (NT_TOTAL * (blockIdx.y + 1)) / NSPLIT - b0;
    const float INF = __int_as_float(0x7f800000);
    const unsigned FULL = 0xffffffffu;

    if (tid == 0) { MBAR_INIT(sm + OFF_MBAR, 1); MBAR_INIT(sm + OFF_MBAR + 8, 1); }
    __syncthreads();

    if (tid == 0) {
        MBAR_EXPECT_TX(sm + OFF_MBAR, 32768u + 32768u + 512u);
        bulk_g2s(sm + OFF_A, g_qt + (size_t)qtile * TILE_HALFS, 32768u, sm + OFF_MBAR);
        bulk_g2s(sm + OFF_B, g_bt + (size_t)b0 * TILE_HALFS, 32768u, sm + OFF_MBAR);
        bulk_g2s(sm + OFF_BSQ, g_bsq + b0 * NTILE, 512u, sm + OFF_MBAR);
        MBAR_EXPECT_TX(sm + OFF_MBAR + 8, 32768u + 512u);
        bulk_g2s(sm + OFF_B + 32768, g_bt + (size_t)(b0 + 1) * TILE_HALFS, 32768u,
                 sm + OFF_MBAR + 8);
        bulk_g2s(sm + OFF_BSQ + 512, g_bsq + (b0 + 1) * NTILE, 512u, sm + OFF_MBAR + 8);
    }

    MBAR_WAIT(sm + OFF_MBAR, 0);

    // preload A fragments (reused for all tiles)
    const int rA   = lane & 15;
    const int shiA = lane >> 4;
    const uint32_t arow = sm + OFF_A + (wid * 16 + rA) * 256;
    uint32_t aF[8][4];
#pragma unroll
    for (int s = 0; s < 8; s++)
        ldsm4(aF[s], arow + ((((uint32_t)(2 * s + shiA)) ^ (uint32_t)(rA & 7)) << 4));

    float heap0[KNN], heap1[KNN];
    float thr0 = INF, thr1 = INF;
#pragma unroll
    for (int i = 0; i < KNN; i++) { heap0[i] = INF; heap1[i] = INF; }

    const int rB   = (lane & 7) + ((lane >> 4) << 3);
    const int shiB = (lane >> 3) & 1;

#pragma unroll 1
    for (int t = 0; t < cnt; t++) {
        const int buf = t & 1;

        if (t > 0) MBAR_WAIT(sm + OFF_MBAR + buf * 8, (t >> 1) & 1);

        const uint32_t Bb = sm + OFF_B + buf * 32768;
        const float2* bq2 = (const float2*)(smem + OFF_BSQ + buf * 512);

#pragma unroll
        for (int half = 0; half < 2; half++) {
            uint32_t acc[8][2];
#pragma unroll
            for (int f = 0; f < 8; f++) { acc[f][0] = 0u; acc[f][1] = 0u; }

#pragma unroll
            for (int s = 0; s < 8; s++) {
                const uint32_t segoff =
                    (((uint32_t)(2 * s + shiB)) ^ (uint32_t)(rB & 7)) << 4;
#pragma unroll
                for (int jb = 0; jb < 4; jb++) {
                    uint32_t bf[4];
                    ldsm4(bf, Bb + ((half * 4 + jb) * 16 + rB) * 256 + segoff);
                    mma16816_f16(acc[2 * jb],     aF[s], bf);
                    mma16816_f16(acc[2 * jb + 1], aF[s], bf + 2);
                }
            }

#pragma unroll
            for (int f = 0; f < 8; f++) {
                float2 bq = bq2[4 * (half * 8 + f) + tig];
                float2 v0 = __half22float2(*(const __half2*)&acc[f][0]);
                float2 v1 = __half22float2(*(const __half2*)&acc[f][1]);
                top9f(fmaf(-2.0f, v0.x, bq.x), heap0, thr0);
                top9f(fmaf(-2.0f, v0.y, bq.y), heap0, thr0);
                top9f(fmaf(-2.0f, v1.x, bq.x), heap1, thr1);
                top9f(fmaf(-2.0f, v1.y, bq.y), heap1, thr1);
            }
        }

        __syncthreads();
        if (t + 2 < cnt && tid == 0) {
            MBAR_EXPECT_TX(sm + OFF_MBAR + buf * 8, 32768u + 512u);
            bulk_g2s(sm + OFF_B + buf * 32768,
                     g_bt + (size_t)(b0 + t + 2) * TILE_HALFS, 32768u,
                     sm + OFF_MBAR + buf * 8);
            bulk_g2s(sm + OFF_BSQ + buf * 512, g_bsq + (b0 + t + 2) * NTILE, 512u,
                     sm + OFF_MBAR + buf * 8);
        }
    }

    // ---- quad merge: lanes tig=1..3 ship their heaps to tig=0
#pragma unroll
    for (int src = 1; src < 4; src++) {
#pragma unroll
        for (int i = 0; i < KNN; i++) {
            float v0 = __shfl_sync(FULL, heap0[i], (lane & ~3) + src);
            float v1 = __shfl_sync(FULL, heap1[i], (lane & ~3) + src);
            if (tig == 0) { top9f(v0, heap0, thr0); top9f(v1, heap1, thr1); }
        }
    }

    if (tig == 0) {
        const int row0 = qbase + wid * 16 + g;
        size_t p0 = ((size_t)blockIdx.y * M_Q + row0) * PART_STRIDE;
        size_t p1 = ((size_t)blockIdx.y * M_Q + row0 + 8) * PART_STRIDE;
#pragma unroll
        for (int r = 0; r < KNN; r++) {
            g_part[p0 + r] = heap0[r];
            g_part[p1 + r] = heap1[r];
        }
    }

    // ---- fused finalize: last CTA of this qtile merges and writes out
    __threadfence();
    __syncthreads();
    int* flag = (int*)(smem + OFF_MBAR + 32);
    if (tid == 0) *flag = atomicAdd(&g_cnt[qtile], 1);
    __syncthreads();
    if (*flag == NSPLIT - 1) {
        if (tid < MTILE) {
            const int qi = qbase + tid;
            float heap[KNN], thr = INF;
#pragma unroll
            for (int i = 0; i < KNN; i++) heap[i] = INF;
#pragma unroll 1
            for (int l = 0; l < NLISTS; l++) {
                const float* p = &g_part[((size_t)l * M_Q + qi) * PART_STRIDE];
#pragma unroll
                for (int r = 0; r < KNN; r++) top9f(p[r], heap, thr);
            }
            float qsq = g_qsq[qi];
            float sum = 0.0f;
#pragma unroll
            for (int i = 0; i < KNN; i++) sum += sqrtf(fmaxf(heap[i] + qsq, 0.0f));
            out[qi] = sum * (1.0f / KNN);
        }
    }
}

// ---------------------------------------------------------------------------
extern "C" void kernel_launch(void* const* d_in, const int* in_sizes, int n_in,
                              void* d_out, int out_size)
{
    const float* q = (const float*)d_in[0];   // features    [4096,128]
    const float* b = (const float*)d_in[1];   // memory_bank [65536,128]
    if (n_in >= 2 && in_sizes[0] > in_sizes[1]) {   // defensive ordering
        const float* tmp = q; q = b; b = tmp;
    }
    float* out = (float*)d_out;

    static uint4* p_bt = nullptr;
    static uint4* p_qt = nullptr;
    static float *p_bsq = nullptr, *p_qsq = nullptr;
    if (!p_bt) {
        cudaGetSymbolAddress((void**)&p_bt, g_bt);
        cudaGetSymbolAddress((void**)&p_qt, g_qt);
        cudaGetSymbolAddress((void**)&p_bsq, g_bsq);
        cudaGetSymbolAddress((void**)&p_qsq, g_qsq);
    }

    cudaFuncSetAttribute(knn_main_kernel,
                         cudaFuncAttributeMaxDynamicSharedMemorySize, SMEM_SZ);

    // single fused pre-pass launch (bank blocks, then query blocks)
    pack_norms_kernel<<<(BCHUNKS + QCHUNKS) / 256, 256>>>(
        (const float4*)b, (const float4*)q, p_bt, p_qt, p_bsq, p_qsq);

    dim3 grid(M_Q / MTILE, NSPLIT);
    knn_main_kernel<<<grid, THREADS, SMEM_SZ>>>(out);
}

// round 17
// speedup vs baseline: 1.8266x; 1.1454x over previous
#include <cuda_runtime.h>
#include <cuda_fp16.h>
#include <cstdint>

#define M_Q   4096
#define N_B   65536
#define D_DIM 128
#define KNN   9
#define MTILE 128
#define NTILE 64
#define NSPLIT 13                     // grid (32,13)=416 CTAs <= 444 slots (3/SM)
#define NT_TOTAL (N_B / NTILE)        // 1024 n-tiles
#define THREADS 256
#define PART_STRIDE 12
#define NLISTS NSPLIT
#define QTILE_HALFS (128 * D_DIM)     // 32KB query tile
#define BTILE_HALFS (64 * D_DIM)      // 16KB bank tile
#define NQTILES (M_Q / MTILE)         // 32
#define BCHUNKS (N_B * 16)            // 16B output chunks for bank
#define QCHUNKS (M_Q * 16)

// ---------------------------------------------------------------------------
// Device-global scratch
// ---------------------------------------------------------------------------
__device__ __align__(16) float g_bsq[N_B];
__device__ __align__(16) float g_qsq[M_Q];
__device__ __align__(16) float g_part[NLISTS * M_Q * PART_STRIDE];
__device__ __align__(16) __half g_bt[(size_t)N_B * D_DIM];   // packed, 64-row tiles
__device__ __align__(16) __half g_qt[(size_t)M_Q * D_DIM];   // packed, 128-row tiles
__device__ int g_cnt[NQTILES];

// ---------------------------------------------------------------------------
// SMEM: A 32KB, B 2x16KB, bsq 2x256B, mbarriers + flag   (66112 B -> 3 CTAs/SM)
// ---------------------------------------------------------------------------
#define OFF_A    0
#define OFF_B    32768
#define OFF_BSQ  (32768 + 2 * 16384)        // 65536
#define OFF_MBAR (OFF_BSQ + 2 * 256)        // 66048
#define SMEM_SZ  (OFF_MBAR + 64)            // 66112

// ---------------------------------------------------------------------------
// PTX helpers (sm_90-baseline)
// ---------------------------------------------------------------------------
__device__ __forceinline__ uint32_t smem_u32(const void* p) {
    uint32_t a;
    asm("{ .reg .u64 t; cvta.to.shared.u64 t, %1; cvt.u32.u64 %0, t; }" : "=r"(a) : "l"(p));
    return a;
}
__device__ __forceinline__ void ldsm4(uint32_t* r, uint32_t addr) {
    asm volatile("ldmatrix.sync.aligned.m8n8.x4.shared.b16 {%0,%1,%2,%3}, [%4];"
                 : "=r"(r[0]), "=r"(r[1]), "=r"(r[2]), "=r"(r[3]) : "r"(addr));
}
__device__ __forceinline__ void mma16816_f16(uint32_t* c, const uint32_t* a, const uint32_t* b) {
    asm volatile(
        "mma.sync.aligned.m16n8k16.row.col.f16.f16.f16.f16 "
        "{%0,%1}, {%2,%3,%4,%5}, {%6,%7}, {%0,%1};"
        : "+r"(c[0]), "+r"(c[1])
        : "r"(a[0]), "r"(a[1]), "r"(a[2]), "r"(a[3]), "r"(b[0]), "r"(b[1]));
}
#define MBAR_INIT(a, c) \
    asm volatile("mbarrier.init.shared.b64 [%0], %1;" :: "r"(a), "r"(c) : "memory")
#define MBAR_EXPECT_TX(a, tx) \
    asm volatile("mbarrier.arrive.expect_tx.shared.b64 _, [%0], %1;" :: "r"(a), "r"(tx) : "memory")
#define MBAR_WAIT(a, ph) do {                                                   \
    asm volatile(                                                               \
        "{\n\t.reg .pred P1;\n\t"                                               \
        "WAIT_LOOP_%=:\n\t"                                                     \
        "mbarrier.try_wait.parity.acquire.cta.shared::cta.b64 P1, [%0], %1, 0x989680;\n\t" \
        "@P1 bra.uni WAIT_DONE_%=;\n\t"                                         \
        "bra.uni WAIT_LOOP_%=;\n\t"                                             \
        "WAIT_DONE_%=:\n\t}"                                                    \
        :: "r"(a), "r"(ph) : "memory");                                         \
} while (0)
__device__ __forceinline__ void bulk_g2s(uint32_t dst, const void* src,
                                         uint32_t bytes, uint32_t mbar) {
    asm volatile(
        "cp.async.bulk.shared::cluster.global.mbarrier::complete_tx::bytes "
        "[%0], [%1], %2, [%3];"
        :: "r"(dst), "l"(src), "r"(bytes), "r"(mbar) : "memory");
}

// ---------------------------------------------------------------------------
// Pre-pass (single launch): fp32 -> fp16 packed tiles + norms for both
// tensors; resets qtile counters. Bank uses 64-row tiles, queries 128-row.
// ---------------------------------------------------------------------------
__device__ __forceinline__ void pack_one(const float4* __restrict__ src,
                                         uint4* __restrict__ dst,
                                         float* __restrict__ nrm, int i,
                                         int rlog) {
    int vec = i >> 4, c = i & 15;
    int rmask = (1 << rlog) - 1;
    int tile = vec >> rlog, r = vec & rmask;
    float4 a = src[2 * i];
    float4 b = src[2 * i + 1];
    __half2 h0 = __floats2half2_rn(a.x, a.y);
    __half2 h1 = __floats2half2_rn(a.z, a.w);
    __half2 h2 = __floats2half2_rn(b.x, b.y);
    __half2 h3 = __floats2half2_rn(b.z, b.w);
    uint4 o;
    o.x = *(uint32_t*)&h0; o.y = *(uint32_t*)&h1;
    o.z = *(uint32_t*)&h2; o.w = *(uint32_t*)&h3;
    uint32_t off = ((uint32_t)tile << (rlog + 8)) + r * 256 + (((uint32_t)(c ^ (r & 7))) << 4);
    dst[off >> 4] = o;

    float s = a.x * a.x + a.y * a.y + a.z * a.z + a.w * a.w
            + b.x * b.x + b.y * b.y + b.z * b.z + b.w * b.w;
#pragma unroll
    for (int offv = 8; offv; offv >>= 1) s += __shfl_xor_sync(0xffffffffu, s, offv);
    if (c == 0) nrm[vec] = s;
}

__global__ void pack_norms_kernel(const float4* __restrict__ bank,
                                  const float4* __restrict__ qry,
                                  uint4* __restrict__ bdst, uint4* __restrict__ qdst,
                                  float* __restrict__ bnrm, float* __restrict__ qnrm) {
    if (blockIdx.x == 0 && threadIdx.x < NQTILES) g_cnt[threadIdx.x] = 0;
    int i = blockIdx.x * blockDim.x + threadIdx.x;
    if (i < BCHUNKS) {
        pack_one(bank, bdst, bnrm, i, 6);          // 64-row tiles
    } else {
        pack_one(qry, qdst, qnrm, i - BCHUNKS, 7); // 128-row tiles
    }
}

// ---------------------------------------------------------------------------
// Streaming top-9
// ---------------------------------------------------------------------------
__device__ __forceinline__ void top9f(float s, float (&h)[KNN], float& thr) {
    if (s < thr) {
        bool done = false;
#pragma unroll
        for (int i = 0; i < KNN; i++)
            if (!done && h[i] == thr) { h[i] = s; done = true; }
        float m = h[0];
#pragma unroll
        for (int i = 1; i < KNN; i++) m = fmaxf(m, h[i]);
        thr = m;
    }
}

// ---------------------------------------------------------------------------
// Main kernel: 3 CTAs/SM (occupancy experiment). grid (32,13), NTILE=64.
// Warp = 16 rows x 64 cols; acc = 8 n8-blocks x 2 regs (fits 84-reg budget).
// ---------------------------------------------------------------------------
__global__ void __launch_bounds__(THREADS, 3) knn_main_kernel(float* __restrict__ out) {
    extern __shared__ char smem[];
    const uint32_t sm = smem_u32(smem);
    const int tid  = threadIdx.x;
    const int wid  = tid >> 5;
    const int lane = tid & 31;
    const int g    = lane >> 2;
    const int tig  = lane & 3;
    const int qtile = blockIdx.x;
    const int qbase = qtile * MTILE;
    const int b0  = (NT_TOTAL * blockIdx.y) / NSPLIT;
    const int cnt = (NT_TOTAL * (blockIdx.y + 1)) / NSPLIT - b0;   // 78 or 79
    const float INF = __int_as_float(0x7f800000);
    const unsigned FULL = 0xffffffffu;

    if (tid == 0) { MBAR_INIT(sm + OFF_MBAR, 1); MBAR_INIT(sm + OFF_MBAR + 8, 1); }
    __syncthreads();

    if (tid == 0) {
        MBAR_EXPECT_TX(sm + OFF_MBAR, 32768u + 16384u + 256u);
        bulk_g2s(sm + OFF_A, g_qt + (size_t)qtile * QTILE_HALFS, 32768u, sm + OFF_MBAR);
        bulk_g2s(sm + OFF_B, g_bt + (size_t)b0 * BTILE_HALFS, 16384u, sm + OFF_MBAR);
        bulk_g2s(sm + OFF_BSQ, g_bsq + b0 * NTILE, 256u, sm + OFF_MBAR);
        MBAR_EXPECT_TX(sm + OFF_MBAR + 8, 16384u + 256u);
        bulk_g2s(sm + OFF_B + 16384, g_bt + (size_t)(b0 + 1) * BTILE_HALFS, 16384u,
                 sm + OFF_MBAR + 8);
        bulk_g2s(sm + OFF_BSQ + 256, g_bsq + (b0 + 1) * NTILE, 256u, sm + OFF_MBAR + 8);
    }

    MBAR_WAIT(sm + OFF_MBAR, 0);

    // preload A fragments (reused for all tiles)
    const int rA   = lane & 15;
    const int shiA = lane >> 4;
    const uint32_t arow = sm + OFF_A + (wid * 16 + rA) * 256;
    uint32_t aF[8][4];
#pragma unroll
    for (int s = 0; s < 8; s++)
        ldsm4(aF[s], arow + ((((uint32_t)(2 * s + shiA)) ^ (uint32_t)(rA & 7)) << 4));

    float heap0[KNN], heap1[KNN];
    float thr0 = INF, thr1 = INF;
#pragma unroll
    for (int i = 0; i < KNN; i++) { heap0[i] = INF; heap1[i] = INF; }

    const int rB   = (lane & 7) + ((lane >> 4) << 3);
    const int shiB = (lane >> 3) & 1;

#pragma unroll 1
    for (int t = 0; t < cnt; t++) {
        const int buf = t & 1;

        if (t > 0) MBAR_WAIT(sm + OFF_MBAR + buf * 8, (t >> 1) & 1);

        const uint32_t Bb = sm + OFF_B + buf * 16384;
        const float2* bq2 = (const float2*)(smem + OFF_BSQ + buf * 256);

        uint32_t acc[8][2];
#pragma unroll
        for (int f = 0; f < 8; f++) { acc[f][0] = 0u; acc[f][1] = 0u; }

#pragma unroll
        for (int s = 0; s < 8; s++) {
            const uint32_t segoff =
                (((uint32_t)(2 * s + shiB)) ^ (uint32_t)(rB & 7)) << 4;
#pragma unroll
            for (int jb = 0; jb < 4; jb++) {
                uint32_t bf[4];
                ldsm4(bf, Bb + (jb * 16 + rB) * 256 + segoff);
                mma16816_f16(acc[2 * jb],     aF[s], bf);
                mma16816_f16(acc[2 * jb + 1], aF[s], bf + 2);
            }
        }

#pragma unroll
        for (int f = 0; f < 8; f++) {
            float2 bq = bq2[4 * f + tig];
            float2 v0 = __half22float2(*(const __half2*)&acc[f][0]);
            float2 v1 = __half22float2(*(const __half2*)&acc[f][1]);
            top9f(fmaf(-2.0f, v0.x, bq.x), heap0, thr0);
            top9f(fmaf(-2.0f, v0.y, bq.y), heap0, thr0);
            top9f(fmaf(-2.0f, v1.x, bq.x), heap1, thr1);
            top9f(fmaf(-2.0f, v1.y, bq.y), heap1, thr1);
        }

        __syncthreads();
        if (t + 2 < cnt && tid == 0) {
            MBAR_EXPECT_TX(sm + OFF_MBAR + buf * 8, 16384u + 256u);
            bulk_g2s(sm + OFF_B + buf * 16384,
                     g_bt + (size_t)(b0 + t + 2) * BTILE_HALFS, 16384u,
                     sm + OFF_MBAR + buf * 8);
            bulk_g2s(sm + OFF_BSQ + buf * 256, g_bsq + (b0 + t + 2) * NTILE, 256u,
                     sm + OFF_MBAR + buf * 8);
        }
    }

    // ---- quad merge: lanes tig=1..3 ship their heaps to tig=0
#pragma unroll
    for (int src = 1; src < 4; src++) {
#pragma unroll
        for (int i = 0; i < KNN; i++) {
            float v0 = __shfl_sync(FULL, heap0[i], (lane & ~3) + src);
            float v1 = __shfl_sync(FULL, heap1[i], (lane & ~3) + src);
            if (tig == 0) { top9f(v0, heap0, thr0); top9f(v1, heap1, thr1); }
        }
    }

    if (tig == 0) {
        const int row0 = qbase + wid * 16 + g;
        size_t p0 = ((size_t)blockIdx.y * M_Q + row0) * PART_STRIDE;
        size_t p1 = ((size_t)blockIdx.y * M_Q + row0 + 8) * PART_STRIDE;
#pragma unroll
        for (int r = 0; r < KNN; r++) {
            g_part[p0 + r] = heap0[r];
            g_part[p1 + r] = heap1[r];
        }
    }

    // ---- fused finalize: last CTA of this qtile merges 13 lists -> out
    __threadfence();
    __syncthreads();
    int* flag = (int*)(smem + OFF_MBAR + 32);
    if (tid == 0) *flag = atomicAdd(&g_cnt[qtile], 1);
    __syncthreads();
    if (*flag == NSPLIT - 1) {
        if (tid < MTILE) {
            const int qi = qbase + tid;
            float heap[KNN], thr = INF;
#pragma unroll
            for (int i = 0; i < KNN; i++) heap[i] = INF;
#pragma unroll 1
            for (int l = 0; l < NLISTS; l++) {
                const float* p = &g_part[((size_t)l * M_Q + qi) * PART_STRIDE];
#pragma unroll
                for (int r = 0; r < KNN; r++) top9f(p[r], heap, thr);
            }
            float qsq = g_qsq[qi];
            float sum = 0.0f;
#pragma unroll
            for (int i = 0; i < KNN; i++) sum += sqrtf(fmaxf(heap[i] + qsq, 0.0f));
            out[qi] = sum * (1.0f / KNN);
        }
    }
}

// ---------------------------------------------------------------------------
extern "C" void kernel_launch(void* const* d_in, const int* in_sizes, int n_in,
                              void* d_out, int out_size)
{
    const float* q = (const float*)d_in[0];   // features    [4096,128]
    const float* b = (const float*)d_in[1];   // memory_bank [65536,128]
    if (n_in >= 2 && in_sizes[0] > in_sizes[1]) {   // defensive ordering
        const float* tmp = q; q = b; b = tmp;
    }
    float* out = (float*)d_out;

    static uint4* p_bt = nullptr;
    static uint4* p_qt = nullptr;
    static float *p_bsq = nullptr, *p_qsq = nullptr;
    if (!p_bt) {
        cudaGetSymbolAddress((void**)&p_bt, g_bt);
        cudaGetSymbolAddress((void**)&p_qt, g_qt);
        cudaGetSymbolAddress((void**)&p_bsq, g_bsq);
        cudaGetSymbolAddress((void**)&p_qsq, g_qsq);
    }

    cudaFuncSetAttribute(knn_main_kernel,
                         cudaFuncAttributeMaxDynamicSharedMemorySize, SMEM_SZ);

    pack_norms_kernel<<<(BCHUNKS + QCHUNKS) / 256, 256>>>(
        (const float4*)b, (const float4*)q, p_bt, p_qt, p_bsq, p_qsq);

    dim3 grid(M_Q / MTILE, NSPLIT);
    knn_main_kernel<<<grid, THREADS, SMEM_SZ>>>(out);
}